// round 1
// baseline (speedup 1.0000x reference)
#include <cuda_runtime.h>
#include <cuda_bf16.h>
#include <float.h>

// ---------------------------------------------------------------------------
// Problem constants
// ---------------------------------------------------------------------------
#define NL    3969      // 63*63 patch positions
#define NCH   5766      // channels
#define HS    504       // b/mask/aux spatial
#define FULLW 512       // padded/scatter resolution
#define PS    16
#define UF    8
#define PD    4

// d_out layout: output (1,3,504,504) | hole (1,6,1,1016,1016) | raw (1,6,3,504,504)
#define OUT_ELEMS   (3*504*504)        // 762048
#define HOLE_ELEMS  (6*1016*1016)      // 6193536
#define RAW_ELEMS   (18*504*504)       // 4572288
#define HOLE_OFF    OUT_ELEMS
#define RAW_OFF     (OUT_ELEMS + HOLE_ELEMS)

// ---------------------------------------------------------------------------
// Device scratch (static allocation — no cudaMalloc allowed)
// ---------------------------------------------------------------------------
__device__ float g_BP [NL * 768];          // b patches        3969 x 768
__device__ float g_MP [23814 * 256];       // mask patches     23814 x 256
__device__ float g_AP [NL * 4608];         // aux patches      3969 x 4608
__device__ float g_C1 [NCH * 768];         // conv1 result     5766 x 768
__device__ float g_C2 [NCH * 256];         // conv2 result     5766 x 256
__device__ float g_BKG[NCH * 1024];        // [bkg | msk]      5766 x 1024
__device__ float g_OM [NL * 1024];         // cos^T @ BKG      3969 x 1024
__device__ float g_RK [NL * 4608];         // gathered aux k   3969 x 4608
__device__ float g_MR [FULLW * FULLW];     // mask_recon @512
__device__ int   g_AMAX[NL];

// ---------------------------------------------------------------------------
// Patch builders: dst[l*(C*256) + c*256 + p*16 + q] = src[c][clamp(8*il+p-4)][clamp(8*jl+q-4)]
// ---------------------------------------------------------------------------
__global__ void build_patches_kernel(const float* __restrict__ src,
                                     float* __restrict__ dst,
                                     int C, int total) {
    int idx = blockIdx.x * blockDim.x + threadIdx.x;
    if (idx >= total) return;
    int per = C << 8;
    int l   = idx / per;
    int r   = idx - l * per;
    int c   = r >> 8;
    int pq  = r & 255;
    int p   = pq >> 4, q = pq & 15;
    int il  = l / 63, jl = l - il * 63;
    int y = il * UF + p - PD; y = min(max(y, 0), HS - 1);
    int x = jl * UF + q - PD; x = min(max(x, 0), HS - 1);
    dst[idx] = src[(c * HS + y) * HS + x];
}

// ---------------------------------------------------------------------------
// argmax over channels per patch position (first-max tie-break)
// ---------------------------------------------------------------------------
__global__ void argmax_kernel(const float* __restrict__ cosim, int* __restrict__ out) {
    int l = blockIdx.x;
    float bv = -FLT_MAX;
    int   bi = NCH;
    for (int ch = threadIdx.x; ch < NCH; ch += 256) {
        float v = cosim[ch * NL + l];
        if (v > bv) { bv = v; bi = ch; }   // ascending ch -> first max kept
    }
    __shared__ float sv[256];
    __shared__ int   si[256];
    sv[threadIdx.x] = bv; si[threadIdx.x] = bi;
    __syncthreads();
    for (int s = 128; s > 0; s >>= 1) {
        if (threadIdx.x < s) {
            float ov = sv[threadIdx.x + s];
            int   oi = si[threadIdx.x + s];
            if (ov > sv[threadIdx.x] ||
                (ov == sv[threadIdx.x] && oi < si[threadIdx.x])) {
                sv[threadIdx.x] = ov; si[threadIdx.x] = oi;
            }
        }
        __syncthreads();
    }
    if (threadIdx.x == 0) out[l] = si[0];
}

// ---------------------------------------------------------------------------
// Generic SIMT SGEMM: C[M,N] = opA @ B (+bias). A via strides (supports both
// row-major weights and m-contiguous cos^T), optional row-gather via ridx.
// B row-major with row stride sb_k. 256 threads = 16x16, each TMxTN.
// ---------------------------------------------------------------------------
template <int BN, int TN>
__launch_bounds__(256)
__global__ void gemm_kernel(int M, int N, int K,
                            const float* __restrict__ A, int sa_m, int sa_k,
                            const float* __restrict__ B, int sb_k,
                            const float* __restrict__ bias,
                            const int*   __restrict__ ridx,
                            float* __restrict__ C, int ldc) {
    const int BM = 128, BK = 16, TM = 8;
    const int tid = threadIdx.x;
    const int tx  = tid & 15;   // n direction
    const int ty  = tid >> 4;   // m direction
    const int m0  = blockIdx.y * BM;
    const int n0  = blockIdx.x * BN;

    __shared__ float As[BK][BM];
    __shared__ float Bs[BK][BN];

    float acc[TM][TN];
#pragma unroll
    for (int i = 0; i < TM; i++)
#pragma unroll
        for (int j = 0; j < TN; j++) acc[i][j] = 0.f;

    for (int k0 = 0; k0 < K; k0 += BK) {
        // ---- load A tile (BM x BK) ----
#pragma unroll
        for (int i = 0; i < (BM * BK) / 256; i++) {
            int t  = tid + i * 256;
            int m  = t & (BM - 1);
            int kk = t >> 7;
            int gm = m0 + m, gk = k0 + kk;
            float v = 0.f;
            if (gm < M && gk < K) {
                int am = ridx ? ridx[gm] : gm;
                v = A[(long)am * sa_m + (long)gk * sa_k];
            }
            As[kk][m] = v;
        }
        // ---- load B tile (BK x BN) ----
#pragma unroll
        for (int i = 0; i < (BN * BK) / 256; i++) {
            int t  = tid + i * 256;
            int n  = t % BN;
            int kk = t / BN;
            int gn = n0 + n, gk = k0 + kk;
            float v = 0.f;
            if (gn < N && gk < K) v = B[(long)gk * sb_k + gn];
            Bs[kk][n] = v;
        }
        __syncthreads();
#pragma unroll
        for (int kk = 0; kk < BK; kk++) {
            float a[TM], b[TN];
#pragma unroll
            for (int i = 0; i < TM; i++) a[i] = As[kk][ty * TM + i];
#pragma unroll
            for (int j = 0; j < TN; j++) b[j] = Bs[kk][tx * TN + j];
#pragma unroll
            for (int i = 0; i < TM; i++)
#pragma unroll
                for (int j = 0; j < TN; j++) acc[i][j] += a[i] * b[j];
        }
        __syncthreads();
    }

#pragma unroll
    for (int i = 0; i < TM; i++) {
        int gm = m0 + ty * TM + i;
        if (gm >= M) continue;
        float bv = 0.f;
        if (bias) bv = bias[ridx ? ridx[gm] : gm];
#pragma unroll
        for (int j = 0; j < TN; j++) {
            int gn = n0 + tx * TN + j;
            if (gn < N) C[(long)gm * ldc + gn] = acc[i][j] + bv;
        }
    }
}

// ---------------------------------------------------------------------------
// BKG[m, 0:768]   = C1[m, :] * (1 - C2[m, col%256])   (bkg_kernel)
// BKG[m, 768:1024]= C2[m, :]                           (msk_kernel, fused GEMM cols)
// ---------------------------------------------------------------------------
__global__ void bkg_kernel(const float* __restrict__ C1, const float* __restrict__ C2,
                           float* __restrict__ BKG, int total) {
    int idx = blockIdx.x * blockDim.x + threadIdx.x;
    if (idx >= total) return;
    int m = idx >> 10;
    int j = idx & 1023;
    float v;
    if (j < 768) v = C1[m * 768 + j] * (1.f - C2[(m << 8) + (j & 255)]);
    else         v = C2[(m << 8) + (j - 768)];
    BKG[idx] = v;
}

// ---------------------------------------------------------------------------
// Overlap-add gather: sum over the <=4 patches covering full-res pixel (Y,X)
// arr row l = i*63+j, element [base + p*16 + q]
// ---------------------------------------------------------------------------
__device__ __forceinline__ float gather_patches(const float* __restrict__ arr,
                                                int Y, int X, int base, int ld) {
    int i1 = Y >> 3, p1 = Y & 7;
    int j1 = X >> 3, q1 = X & 7;
    float s = 0.f;
#pragma unroll
    for (int dy = 0; dy < 2; dy++) {
        int i = i1 - dy;
        if (i < 0 || i > 62) continue;
        int p = p1 + 8 * dy;
#pragma unroll
        for (int dx = 0; dx < 2; dx++) {
            int j = j1 - dx;
            if (j < 0 || j > 62) continue;
            int q = q1 + 8 * dx;
            s += arr[(long)(i * 63 + j) * ld + base + p * 16 + q];
        }
    }
    return s;
}

// weight_map coverage count per coordinate (separable): #patches covering y
__device__ __forceinline__ int cov(int y) {
    int lo = (y <= 15) ? 0 : ((y - 8) >> 3);
    int hi = min(62, y >> 3);
    return hi - lo + 1;
}

__global__ void mr_kernel(const float* __restrict__ OM, float* __restrict__ MR) {
    int idx = blockIdx.x * blockDim.x + threadIdx.x;
    if (idx >= FULLW * FULLW) return;
    int y = idx >> 9, x = idx & 511;
    MR[idx] = gather_patches(OM, y, x, 768, 1024);
}

__global__ void out_epi(const float* __restrict__ OM, float* __restrict__ out) {
    int idx = blockIdx.x * blockDim.x + threadIdx.x;
    if (idx >= OUT_ELEMS) return;
    int oc = idx / 254016;
    int r  = idx - oc * 254016;
    int Y  = r / 504 + PD;
    int X  = r - (r / 504) * 504 + PD;
    out[idx] = gather_patches(OM, Y, X, oc << 8, 1024);
}

__global__ void hole_epi(const float* __restrict__ MR,
                         const float* __restrict__ up2w, const float* __restrict__ up2b,
                         const float* __restrict__ up3w, const float* __restrict__ up3b,
                         float* __restrict__ out) {
    int idx = blockIdx.x * blockDim.x + threadIdx.x;
    if (idx >= HOLE_ELEMS) return;
    int c  = idx / 1032256;
    int r  = idx - c * 1032256;
    int Yh = r / 1016;
    int Xh = r - Yh * 1016;
    int Yu = Yh + PD, Xu = Xh + PD;          // coords in 1024-space
    int y = Yu >> 1, ky = Yu & 1;
    int x = Xu >> 1, kx = Xu & 1;
    float mr = MR[(y << 9) + x];
    float wm = (float)(cov(y) * cov(x));
    float num = mr * up2w[c * 4 + ky * 2 + kx] + up2b[c];
    float den = wm * up3w[ky * 2 + kx] + up3b[0];
    out[idx] = num / den;
}

__global__ void raw_epi(const float* __restrict__ RK, float* __restrict__ out) {
    int idx = blockIdx.x * blockDim.x + threadIdx.x;
    if (idx >= RAW_ELEMS) return;
    int oc = idx / 254016;
    int r  = idx - oc * 254016;
    int Y  = r / 504 + PD;
    int X  = r - (r / 504) * 504 + PD;
    float s  = gather_patches(RK, Y, X, oc << 8, 4608);
    float wm = (float)(cov(Y) * cov(X));
    out[idx] = s / wm;
}

// ---------------------------------------------------------------------------
// Host orchestration
// ---------------------------------------------------------------------------
extern "C" void kernel_launch(void* const* d_in, const int* in_sizes, int n_in,
                              void* d_out, int out_size) {
    (void)in_sizes; (void)n_in; (void)out_size;
    const float* cosim = (const float*)d_in[0];
    const float* b     = (const float*)d_in[1];
    const float* mask  = (const float*)d_in[2];
    const float* aux   = (const float*)d_in[3];
    const float* w1    = (const float*)d_in[4];
    const float* b1    = (const float*)d_in[5];
    const float* w2    = (const float*)d_in[6];
    const float* b2    = (const float*)d_in[7];
    const float* wa    = (const float*)d_in[8];
    const float* ba    = (const float*)d_in[9];
    const float* up2w  = (const float*)d_in[10];
    const float* up2b  = (const float*)d_in[11];
    const float* up3w  = (const float*)d_in[12];
    const float* up3b  = (const float*)d_in[13];
    float* out = (float*)d_out;

    float *BP, *MP, *AP, *C1, *C2, *BKG, *OM, *RK, *MR;
    int* AM;
    cudaGetSymbolAddress((void**)&BP,  g_BP);
    cudaGetSymbolAddress((void**)&MP,  g_MP);
    cudaGetSymbolAddress((void**)&AP,  g_AP);
    cudaGetSymbolAddress((void**)&C1,  g_C1);
    cudaGetSymbolAddress((void**)&C2,  g_C2);
    cudaGetSymbolAddress((void**)&BKG, g_BKG);
    cudaGetSymbolAddress((void**)&OM,  g_OM);
    cudaGetSymbolAddress((void**)&RK,  g_RK);
    cudaGetSymbolAddress((void**)&MR,  g_MR);
    cudaGetSymbolAddress((void**)&AM,  g_AMAX);

    // patch matrices
    {
        int t = NL * 768;
        build_patches_kernel<<<(t + 255) / 256, 256>>>(b, BP, 3, t);
    }
    {
        int t = 23814 * 256;
        build_patches_kernel<<<(t + 255) / 256, 256>>>(mask, MP, 6, t);
    }
    {
        int t = NL * 4608;
        build_patches_kernel<<<(t + 255) / 256, 256>>>(aux, AP, 18, t);
    }

    // hardmax indices
    argmax_kernel<<<NL, 256>>>(cosim, AM);

    // GEMM1: C1 = conv1_w(5766x3969) @ BP(3969x768) + b1
    {
        dim3 grid(768 / 128, (NCH + 127) / 128);
        gemm_kernel<128, 8><<<grid, 256>>>(NCH, 768, NL,
                                           w1, NL, 1, BP, 768, b1, nullptr, C1, 768);
    }
    // GEMM2: C2 = conv2_w(5766x23814) @ MP(23814x256) + b2
    {
        dim3 grid(256 / 64, (NCH + 127) / 128);
        gemm_kernel<64, 4><<<grid, 256>>>(NCH, 256, 23814,
                                          w2, 23814, 1, MP, 256, b2, nullptr, C2, 256);
    }
    // fuse bkg = C1*(1-C2) and append C2 columns
    {
        int t = NCH * 1024;
        bkg_kernel<<<(t + 255) / 256, 256>>>(C1, C2, BKG, t);
    }
    // GEMM5 (gathered rows): RK = convaux_w[amax] @ AP + ba[amax]
    {
        dim3 grid(4608 / 128, (NL + 127) / 128);
        gemm_kernel<128, 8><<<grid, 256>>>(NL, 4608, NL,
                                           wa, NL, 1, AP, 4608, ba, AM, RK, 4608);
    }
    // GEMM3: OM = cos^T(3969x5766) @ BKG(5766x1024)
    {
        dim3 grid(1024 / 128, (NL + 127) / 128);
        gemm_kernel<128, 8><<<grid, 256>>>(NL, 1024, NCH,
                                           cosim, 1, NL, BKG, 1024, nullptr, nullptr, OM, 1024);
    }

    // mask_recon at 512 resolution
    mr_kernel<<<(FULLW * FULLW + 255) / 256, 256>>>(OM, MR);

    // outputs
    out_epi <<<(OUT_ELEMS  + 255) / 256, 256>>>(OM, out);
    hole_epi<<<(HOLE_ELEMS + 255) / 256, 256>>>(MR, up2w, up2b, up3w, up3b, out + HOLE_OFF);
    raw_epi <<<(RAW_ELEMS  + 255) / 256, 256>>>(RK, out + RAW_OFF);
}

// round 2
// speedup vs baseline: 1.0019x; 1.0019x over previous
#include <cuda_runtime.h>
#include <cuda_bf16.h>
#include <float.h>

// ---------------------------------------------------------------------------
// Problem constants
// ---------------------------------------------------------------------------
#define NL    3969      // 63*63 patch positions
#define NCH   5766      // channels
#define HS    504       // b/mask/aux spatial
#define FULLW 512       // padded/scatter resolution
#define PS    16
#define UF    8
#define PD    4

// d_out layout: output (1,3,504,504) | hole (1,6,1,1016,1016) | raw (1,6,3,504,504)
#define OUT_ELEMS   (3*504*504)        // 762048
#define HOLE_ELEMS  (6*1016*1016)      // 6193536
#define RAW_ELEMS   (18*504*504)       // 4572288
#define HOLE_OFF    OUT_ELEMS
#define RAW_OFF     (OUT_ELEMS + HOLE_ELEMS)

// ---------------------------------------------------------------------------
// Device scratch (static allocation — no cudaMalloc allowed)
// ---------------------------------------------------------------------------
__device__ float g_BP [NL * 768];          // b patches        3969 x 768
__device__ float g_MP [23814 * 256];       // mask patches     23814 x 256
__device__ float g_AP [NL * 4608];         // aux patches      3969 x 4608
__device__ float g_C1 [NCH * 768];         // conv1 result     5766 x 768
__device__ float g_C2 [NCH * 256];         // conv2 result     5766 x 256
__device__ float g_BKG[NCH * 1024];        // [bkg | msk]      5766 x 1024
__device__ float g_OM [NL * 1024];         // cos^T @ BKG      3969 x 1024
__device__ float g_RK [NL * 4608];         // gathered aux k   3969 x 4608
__device__ float g_MR [FULLW * FULLW];     // mask_recon @512
__device__ int   g_AMAX[NL];

// ---------------------------------------------------------------------------
// Patch builders: dst[l*(C*256) + c*256 + p*16 + q] = src[c][clamp(8*il+p-4)][clamp(8*jl+q-4)]
// ---------------------------------------------------------------------------
__global__ void build_patches_kernel(const float* __restrict__ src,
                                     float* __restrict__ dst,
                                     int C, int total) {
    int idx = blockIdx.x * blockDim.x + threadIdx.x;
    if (idx >= total) return;
    int per = C << 8;
    int l   = idx / per;
    int r   = idx - l * per;
    int c   = r >> 8;
    int pq  = r & 255;
    int p   = pq >> 4, q = pq & 15;
    int il  = l / 63, jl = l - il * 63;
    int y = il * UF + p - PD; y = min(max(y, 0), HS - 1);
    int x = jl * UF + q - PD; x = min(max(x, 0), HS - 1);
    dst[idx] = src[(c * HS + y) * HS + x];
}

// ---------------------------------------------------------------------------
// argmax over channels per patch position (first-max tie-break)
// ---------------------------------------------------------------------------
__global__ void argmax_kernel(const float* __restrict__ cosim, int* __restrict__ out) {
    int l = blockIdx.x;
    float bv = -FLT_MAX;
    int   bi = NCH;
    for (int ch = threadIdx.x; ch < NCH; ch += 256) {
        float v = cosim[ch * NL + l];
        if (v > bv) { bv = v; bi = ch; }   // ascending ch -> first max kept
    }
    __shared__ float sv[256];
    __shared__ int   si[256];
    sv[threadIdx.x] = bv; si[threadIdx.x] = bi;
    __syncthreads();
    for (int s = 128; s > 0; s >>= 1) {
        if (threadIdx.x < s) {
            float ov = sv[threadIdx.x + s];
            int   oi = si[threadIdx.x + s];
            if (ov > sv[threadIdx.x] ||
                (ov == sv[threadIdx.x] && oi < si[threadIdx.x])) {
                sv[threadIdx.x] = ov; si[threadIdx.x] = oi;
            }
        }
        __syncthreads();
    }
    if (threadIdx.x == 0) out[l] = si[0];
}

// ---------------------------------------------------------------------------
// Generic SIMT SGEMM: C[M,N] = opA @ B (+bias). A via strides (supports both
// row-major weights and m-contiguous cos^T), optional row-gather via ridx.
// B row-major with row stride sb_k. 256 threads = 16x16, each TMxTN.
// ---------------------------------------------------------------------------
template <int BN, int TN>
__launch_bounds__(256)
__global__ void gemm_kernel(int M, int N, int K,
                            const float* __restrict__ A, int sa_m, int sa_k,
                            const float* __restrict__ B, int sb_k,
                            const float* __restrict__ bias,
                            const int*   __restrict__ ridx,
                            float* __restrict__ C, int ldc) {
    const int BM = 128, BK = 16, TM = 8;
    const int tid = threadIdx.x;
    const int tx  = tid & 15;   // n direction
    const int ty  = tid >> 4;   // m direction
    const int m0  = blockIdx.y * BM;
    const int n0  = blockIdx.x * BN;

    __shared__ float As[BK][BM];
    __shared__ float Bs[BK][BN];

    float acc[TM][TN];
#pragma unroll
    for (int i = 0; i < TM; i++)
#pragma unroll
        for (int j = 0; j < TN; j++) acc[i][j] = 0.f;

    for (int k0 = 0; k0 < K; k0 += BK) {
        // ---- load A tile (BM x BK) ----
#pragma unroll
        for (int i = 0; i < (BM * BK) / 256; i++) {
            int t  = tid + i * 256;
            int m  = t & (BM - 1);
            int kk = t >> 7;
            int gm = m0 + m, gk = k0 + kk;
            float v = 0.f;
            if (gm < M && gk < K) {
                int am = ridx ? ridx[gm] : gm;
                v = A[(long)am * sa_m + (long)gk * sa_k];
            }
            As[kk][m] = v;
        }
        // ---- load B tile (BK x BN) ----
#pragma unroll
        for (int i = 0; i < (BN * BK) / 256; i++) {
            int t  = tid + i * 256;
            int n  = t % BN;
            int kk = t / BN;
            int gn = n0 + n, gk = k0 + kk;
            float v = 0.f;
            if (gn < N && gk < K) v = B[(long)gk * sb_k + gn];
            Bs[kk][n] = v;
        }
        __syncthreads();
#pragma unroll
        for (int kk = 0; kk < BK; kk++) {
            float a[TM], b[TN];
#pragma unroll
            for (int i = 0; i < TM; i++) a[i] = As[kk][ty * TM + i];
#pragma unroll
            for (int j = 0; j < TN; j++) b[j] = Bs[kk][tx * TN + j];
#pragma unroll
            for (int i = 0; i < TM; i++)
#pragma unroll
                for (int j = 0; j < TN; j++) acc[i][j] += a[i] * b[j];
        }
        __syncthreads();
    }

#pragma unroll
    for (int i = 0; i < TM; i++) {
        int gm = m0 + ty * TM + i;
        if (gm >= M) continue;
        float bv = 0.f;
        if (bias) bv = bias[ridx ? ridx[gm] : gm];
#pragma unroll
        for (int j = 0; j < TN; j++) {
            int gn = n0 + tx * TN + j;
            if (gn < N) C[(long)gm * ldc + gn] = acc[i][j] + bv;
        }
    }
}

// ---------------------------------------------------------------------------
// BKG[m, 0:768]   = C1[m, :] * (1 - C2[m, col%256])   (bkg_kernel)
// BKG[m, 768:1024]= C2[m, :]                           (msk_kernel, fused GEMM cols)
// ---------------------------------------------------------------------------
__global__ void bkg_kernel(const float* __restrict__ C1, const float* __restrict__ C2,
                           float* __restrict__ BKG, int total) {
    int idx = blockIdx.x * blockDim.x + threadIdx.x;
    if (idx >= total) return;
    int m = idx >> 10;
    int j = idx & 1023;
    float v;
    if (j < 768) v = C1[m * 768 + j] * (1.f - C2[(m << 8) + (j & 255)]);
    else         v = C2[(m << 8) + (j - 768)];
    BKG[idx] = v;
}

// ---------------------------------------------------------------------------
// Overlap-add gather: sum over the <=4 patches covering full-res pixel (Y,X)
// arr row l = i*63+j, element [base + p*16 + q]
// ---------------------------------------------------------------------------
__device__ __forceinline__ float gather_patches(const float* __restrict__ arr,
                                                int Y, int X, int base, int ld) {
    int i1 = Y >> 3, p1 = Y & 7;
    int j1 = X >> 3, q1 = X & 7;
    float s = 0.f;
#pragma unroll
    for (int dy = 0; dy < 2; dy++) {
        int i = i1 - dy;
        if (i < 0 || i > 62) continue;
        int p = p1 + 8 * dy;
#pragma unroll
        for (int dx = 0; dx < 2; dx++) {
            int j = j1 - dx;
            if (j < 0 || j > 62) continue;
            int q = q1 + 8 * dx;
            s += arr[(long)(i * 63 + j) * ld + base + p * 16 + q];
        }
    }
    return s;
}

// weight_map coverage count per coordinate (separable): #patches covering y
__device__ __forceinline__ int cov(int y) {
    int lo = (y <= 15) ? 0 : ((y - 8) >> 3);
    int hi = min(62, y >> 3);
    return hi - lo + 1;
}

__global__ void mr_kernel(const float* __restrict__ OM, float* __restrict__ MR) {
    int idx = blockIdx.x * blockDim.x + threadIdx.x;
    if (idx >= FULLW * FULLW) return;
    int y = idx >> 9, x = idx & 511;
    MR[idx] = gather_patches(OM, y, x, 768, 1024);
}

__global__ void out_epi(const float* __restrict__ OM, float* __restrict__ out) {
    int idx = blockIdx.x * blockDim.x + threadIdx.x;
    if (idx >= OUT_ELEMS) return;
    int oc = idx / 254016;
    int r  = idx - oc * 254016;
    int Y  = r / 504 + PD;
    int X  = r - (r / 504) * 504 + PD;
    out[idx] = gather_patches(OM, Y, X, oc << 8, 1024);
}

__global__ void hole_epi(const float* __restrict__ MR,
                         const float* __restrict__ up2w, const float* __restrict__ up2b,
                         const float* __restrict__ up3w, const float* __restrict__ up3b,
                         float* __restrict__ out) {
    int idx = blockIdx.x * blockDim.x + threadIdx.x;
    if (idx >= HOLE_ELEMS) return;
    int c  = idx / 1032256;
    int r  = idx - c * 1032256;
    int Yh = r / 1016;
    int Xh = r - Yh * 1016;
    int Yu = Yh + PD, Xu = Xh + PD;          // coords in 1024-space
    int y = Yu >> 1, ky = Yu & 1;
    int x = Xu >> 1, kx = Xu & 1;
    float mr = MR[(y << 9) + x];
    float wm = (float)(cov(y) * cov(x));
    float num = mr * up2w[c * 4 + ky * 2 + kx] + up2b[c];
    float den = wm * up3w[ky * 2 + kx] + up3b[0];
    out[idx] = num / den;
}

__global__ void raw_epi(const float* __restrict__ RK, float* __restrict__ out) {
    int idx = blockIdx.x * blockDim.x + threadIdx.x;
    if (idx >= RAW_ELEMS) return;
    int oc = idx / 254016;
    int r  = idx - oc * 254016;
    int Y  = r / 504 + PD;
    int X  = r - (r / 504) * 504 + PD;
    float s  = gather_patches(RK, Y, X, oc << 8, 4608);
    float wm = (float)(cov(Y) * cov(X));
    out[idx] = s / wm;
}

// ---------------------------------------------------------------------------
// Host orchestration
// ---------------------------------------------------------------------------
extern "C" void kernel_launch(void* const* d_in, const int* in_sizes, int n_in,
                              void* d_out, int out_size) {
    (void)in_sizes; (void)n_in; (void)out_size;
    const float* cosim = (const float*)d_in[0];
    const float* b     = (const float*)d_in[1];
    const float* mask  = (const float*)d_in[2];
    const float* aux   = (const float*)d_in[3];
    const float* w1    = (const float*)d_in[4];
    const float* b1    = (const float*)d_in[5];
    const float* w2    = (const float*)d_in[6];
    const float* b2    = (const float*)d_in[7];
    const float* wa    = (const float*)d_in[8];
    const float* ba    = (const float*)d_in[9];
    const float* up2w  = (const float*)d_in[10];
    const float* up2b  = (const float*)d_in[11];
    const float* up3w  = (const float*)d_in[12];
    const float* up3b  = (const float*)d_in[13];
    float* out = (float*)d_out;

    float *BP, *MP, *AP, *C1, *C2, *BKG, *OM, *RK, *MR;
    int* AM;
    cudaGetSymbolAddress((void**)&BP,  g_BP);
    cudaGetSymbolAddress((void**)&MP,  g_MP);
    cudaGetSymbolAddress((void**)&AP,  g_AP);
    cudaGetSymbolAddress((void**)&C1,  g_C1);
    cudaGetSymbolAddress((void**)&C2,  g_C2);
    cudaGetSymbolAddress((void**)&BKG, g_BKG);
    cudaGetSymbolAddress((void**)&OM,  g_OM);
    cudaGetSymbolAddress((void**)&RK,  g_RK);
    cudaGetSymbolAddress((void**)&MR,  g_MR);
    cudaGetSymbolAddress((void**)&AM,  g_AMAX);

    // patch matrices
    {
        int t = NL * 768;
        build_patches_kernel<<<(t + 255) / 256, 256>>>(b, BP, 3, t);
    }
    {
        int t = 23814 * 256;
        build_patches_kernel<<<(t + 255) / 256, 256>>>(mask, MP, 6, t);
    }
    {
        int t = NL * 4608;
        build_patches_kernel<<<(t + 255) / 256, 256>>>(aux, AP, 18, t);
    }

    // hardmax indices
    argmax_kernel<<<NL, 256>>>(cosim, AM);

    // GEMM1: C1 = conv1_w(5766x3969) @ BP(3969x768) + b1
    {
        dim3 grid(768 / 128, (NCH + 127) / 128);
        gemm_kernel<128, 8><<<grid, 256>>>(NCH, 768, NL,
                                           w1, NL, 1, BP, 768, b1, nullptr, C1, 768);
    }
    // GEMM2: C2 = conv2_w(5766x23814) @ MP(23814x256) + b2
    {
        dim3 grid(256 / 64, (NCH + 127) / 128);
        gemm_kernel<64, 4><<<grid, 256>>>(NCH, 256, 23814,
                                          w2, 23814, 1, MP, 256, b2, nullptr, C2, 256);
    }
    // fuse bkg = C1*(1-C2) and append C2 columns
    {
        int t = NCH * 1024;
        bkg_kernel<<<(t + 255) / 256, 256>>>(C1, C2, BKG, t);
    }
    // GEMM5 (gathered rows): RK = convaux_w[amax] @ AP + ba[amax]
    {
        dim3 grid(4608 / 128, (NL + 127) / 128);
        gemm_kernel<128, 8><<<grid, 256>>>(NL, 4608, NL,
                                           wa, NL, 1, AP, 4608, ba, AM, RK, 4608);
    }
    // GEMM3: OM = cos^T(3969x5766) @ BKG(5766x1024)
    {
        dim3 grid(1024 / 128, (NL + 127) / 128);
        gemm_kernel<128, 8><<<grid, 256>>>(NL, 1024, NCH,
                                           cosim, 1, NL, BKG, 1024, nullptr, nullptr, OM, 1024);
    }

    // mask_recon at 512 resolution
    mr_kernel<<<(FULLW * FULLW + 255) / 256, 256>>>(OM, MR);

    // outputs
    out_epi <<<(OUT_ELEMS  + 255) / 256, 256>>>(OM, out);
    hole_epi<<<(HOLE_ELEMS + 255) / 256, 256>>>(MR, up2w, up2b, up3w, up3b, out + HOLE_OFF);
    raw_epi <<<(RAW_ELEMS  + 255) / 256, 256>>>(RK, out + RAW_OFF);
}

// round 4
// speedup vs baseline: 4.6904x; 4.6813x over previous
#include <cuda_runtime.h>
#include <cuda_bf16.h>
#include <float.h>
#include <cstdint>

#define NL    3969
#define NCH   5766
#define HS    504
#define OUT_ELEMS   (3*504*504)
#define HOLE_ELEMS  (6*1016*1016)
#define RAW_ELEMS   (18*504*504)
#define HOLE_OFF    OUT_ELEMS
#define RAW_OFF     (OUT_ELEMS + HOLE_ELEMS)

#define K1 3969
#define KT1 187
#define K2 23814
#define KT2 1117
#define K3 5766
#define KT3 271

typedef __nv_bfloat16 bf16;

// zero-initialized at module load; pad regions are never written
__device__ __align__(128) bf16 g_A1[(size_t)5888*11968];
__device__ __align__(128) bf16 g_A2[(size_t)5888*71488];
__device__ __align__(128) bf16 g_AA[(size_t)4096*11968];
__device__ __align__(128) bf16 g_A3[(size_t)4096*17344];
__device__ __align__(128) bf16 g_B1[(size_t)768*11968];
__device__ __align__(128) bf16 g_B2[(size_t)256*71488];
__device__ __align__(128) bf16 g_BA[(size_t)4608*11968];
__device__ __align__(128) bf16 g_B3[(size_t)1024*17344];
__device__ __align__(128) float g_C1[(size_t)NCH*768];
__device__ __align__(128) float g_C2[(size_t)NCH*256];
__device__ __align__(128) float g_P2[(size_t)4*NCH*256];
__device__ __align__(128) float g_OM[(size_t)NL*1024];
__device__ __align__(128) float g_RK[(size_t)NL*4608];
__device__ __align__(128) float g_MR[512*512];
__device__ int g_AMAX[NL];

__device__ __forceinline__ uint32_t smem_u32(const void* p) {
    uint32_t a;
    asm("{ .reg .u64 t; cvta.to.shared.u64 t, %1; cvt.u32.u64 %0, t; }" : "=r"(a) : "l"(p));
    return a;
}

// swizzled byte offset of element (row, col) inside a 128x64 bf16 operand block
__device__ __forceinline__ uint32_t swz(int row, int col) {
    uint32_t byte = ((uint32_t)(row >> 3) << 10) | ((uint32_t)(row & 7) << 7) | ((uint32_t)col << 1);
    return byte ^ ((byte >> 3) & 0x70);
}

// GMEM operand index: 128-row x 64-col blocks of 16KB, same swizzle inside
__device__ __forceinline__ size_t op_idx(int row, int k3, int Kt) {
    size_t blk = ((size_t)(row >> 7) * (size_t)Kt + (size_t)(k3 >> 6)) << 13;
    return blk + (size_t)(swz(row & 127, k3 & 63) >> 1);
}
// A segments: [hi, lo, hi]; B segments: [hi, hi, lo]  (A@B ~= AhBh + AlBh + AhBl)
__device__ __forceinline__ void split_write_A(bf16* d, int r, int k, int K, int Kt, float v) {
    bf16 hi = __float2bfloat16(v);
    bf16 lo = __float2bfloat16(v - __bfloat162float(hi));
    d[op_idx(r, k, Kt)] = hi; d[op_idx(r, K + k, Kt)] = lo; d[op_idx(r, 2*K + k, Kt)] = hi;
}
__device__ __forceinline__ void split_write_B(bf16* d, int r, int k, int K, int Kt, float v) {
    bf16 hi = __float2bfloat16(v);
    bf16 lo = __float2bfloat16(v - __bfloat162float(hi));
    d[op_idx(r, k, Kt)] = hi; d[op_idx(r, K + k, Kt)] = hi; d[op_idx(r, 2*K + k, Kt)] = lo;
}

__global__ void split_rowmajor(const float* __restrict__ src, bf16* __restrict__ dst,
                               int M, int K, int Kt, const int* __restrict__ ridx) {
    long idx = (long)blockIdx.x * blockDim.x + threadIdx.x;
    if (idx >= (long)M * K) return;
    int m = (int)(idx / K), k = (int)(idx - (long)m * K);
    int sm = ridx ? ridx[m] : m;
    split_write_A(dst, m, k, K, Kt, src[(size_t)sm * K + k]);
}

// mode 0: row n=c*256+pq, k=l (b/aux).  mode 1: row n=pq, k=l*C+c (mask)
__global__ void split_patches(const float* __restrict__ img, bf16* __restrict__ dst,
                              int C, int Nr, int K, int Kt, int mode) {
    long idx = (long)blockIdx.x * blockDim.x + threadIdx.x;
    if (idx >= (long)Nr * K) return;
    int n = (int)(idx / K), k = (int)(idx - (long)n * K);
    int c, l, pq;
    if (mode == 0) { c = n >> 8; pq = n & 255; l = k; }
    else           { pq = n; l = k / C; c = k - l * C; }
    int p = pq >> 4, q = pq & 15;
    int il = l / 63, jl = l - il * 63;
    int y = min(max(il * 8 + p - 4, 0), HS - 1);
    int x = min(max(jl * 8 + q - 4, 0), HS - 1);
    split_write_B(dst, n, k, K, Kt, img[((size_t)c * HS + y) * HS + x]);
}

// cos^T as A operand: rows m=l, k'=3*ch concat; seg1 -> lo
__global__ __launch_bounds__(128) void transsplit_cos(const float* __restrict__ cosim,
                                                      bf16* __restrict__ dst) {
    __shared__ __align__(16) bf16 obuf[8192];
    int kt = blockIdx.x, mt = blockIdx.y, tid = threadIdx.x;
    int m = mt * 128 + tid;
    for (int c = 0; c < 64; c++) {
        int k3 = kt * 64 + c;
        int seg = k3 / K3, k = k3 - seg * K3;
        float v = 0.f;
        if (seg < 3 && m < NL) v = cosim[(size_t)k * NL + m];
        bf16 hv = __float2bfloat16(v);
        bf16 o = (seg == 1) ? __float2bfloat16(v - __bfloat162float(hv)) : hv;
        obuf[swz(tid, c) >> 1] = o;
    }
    __syncthreads();
    const int4* s4 = (const int4*)obuf;
    int4* d4 = (int4*)(dst + (((size_t)mt * KT3 + kt) << 13));
    for (int i = tid; i < 1024; i += 128) d4[i] = s4[i];
}

// bkg^T as B operand: rows n=j(0..1023), k'=3*ch; seg2 -> lo
__global__ __launch_bounds__(128) void transsplit_bkg(const float* __restrict__ C1,
                                                      const float* __restrict__ C2,
                                                      bf16* __restrict__ dst) {
    __shared__ __align__(16) bf16 obuf[8192];
    int kt = blockIdx.x, nt = blockIdx.y, tid = threadIdx.x;
    int nn = nt * 128 + tid;
    for (int c = 0; c < 64; c++) {
        int k3 = kt * 64 + c;
        int seg = k3 / K3, ch = k3 - seg * K3;
        float v = 0.f;
        if (seg < 3) {
            if (nn < 768) v = C1[(size_t)ch * 768 + nn] * (1.f - C2[((size_t)ch << 8) + (nn & 255)]);
            else          v = C2[((size_t)ch << 8) + (nn - 768)];
        }
        bf16 hv = __float2bfloat16(v);
        bf16 o = (seg == 2) ? __float2bfloat16(v - __bfloat162float(hv)) : hv;
        obuf[swz(tid, c) >> 1] = o;
    }
    __syncthreads();
    const int4* s4 = (const int4*)obuf;
    int4* d4 = (int4*)(dst + (((size_t)nt * KT3 + kt) << 13));
    for (int i = tid; i < 1024; i += 128) d4[i] = s4[i];
}

// ---------------------------------------------------------------------------
// HMMA bf16 GEMM: 128x128 block, 8 warps (2x4), K chunks of 64, cp.async x2
// ---------------------------------------------------------------------------
__global__ __launch_bounds__(256) void gemm_tc(
    const bf16* __restrict__ Aop, const bf16* __restrict__ Bop,
    int Kt, int cpk, int ntn,
    float* __restrict__ Cout, int M, int ldc,
    const float* __restrict__ bias, const int* __restrict__ bidx,
    long partstride) {
    extern __shared__ char sm[];   // 2 stages x (A 16KB + B 16KB)
    const int tid = threadIdx.x, wid = tid >> 5, lane = tid & 31;
    const int mt = blockIdx.x / ntn, nt = blockIdx.x - mt * ntn;
    const int k0 = blockIdx.y * cpk, k1 = min(Kt, k0 + cpk);
    const int wm = wid >> 2, wn = wid & 3;   // warp tile: 64M x 32N

    uint32_t sbase = smem_u32(sm);

    // ldmatrix lane address components (PTX frag order verified)
    int sel = lane >> 3, l7 = lane & 7;
    int arow = wm * 64 + l7 + (sel & 1) * 8;   // A: sel&1 -> +8 rows, sel>>1 -> +8 cols
    int acol = (sel >> 1) * 8;
    int brow = wn * 32 + l7 + (sel >> 1) * 8;  // B: sel>>1 -> +8 rows(n), sel&1 -> +8 cols(k)
    int bcol = (sel & 1) * 8;

    float acc[4][4][4];
#pragma unroll
    for (int i = 0; i < 4; i++)
#pragma unroll
        for (int j = 0; j < 4; j++)
#pragma unroll
            for (int v = 0; v < 4; v++) acc[i][j][v] = 0.f;

    auto load_chunk = [&](int kc, int s) {
        const char* asrc = (const char*)(Aop + (((size_t)mt * Kt + kc) << 13));
        const char* bsrc = (const char*)(Bop + (((size_t)nt * Kt + kc) << 13));
        uint32_t sa = sbase + (uint32_t)s * 32768u;
        uint32_t sb = sa + 16384u;
        int off = tid * 16;
#pragma unroll
        for (int i = 0; i < 4; i++) {
            asm volatile("cp.async.cg.shared.global [%0], [%1], 16;" :: "r"(sa + off), "l"(asrc + off));
            asm volatile("cp.async.cg.shared.global [%0], [%1], 16;" :: "r"(sb + off), "l"(bsrc + off));
            off += 4096;
        }
        asm volatile("cp.async.commit_group;");
    };

    load_chunk(k0, 0);
    for (int i = k0; i < k1; i++) {
        int s = (i - k0) & 1;
        if (i + 1 < k1) {
            load_chunk(i + 1, s ^ 1);
            asm volatile("cp.async.wait_group 1;");
        } else {
            asm volatile("cp.async.wait_group 0;");
        }
        __syncthreads();

        uint32_t sa = sbase + (uint32_t)s * 32768u;
        uint32_t sb = sa + 16384u;
#pragma unroll
        for (int ks = 0; ks < 4; ks++) {
            uint32_t bf[2][4];
#pragma unroll
            for (int ntl = 0; ntl < 2; ntl++) {
                uint32_t addr = sb + swz(brow + ntl * 16, bcol + ks * 16);
                asm volatile("ldmatrix.sync.aligned.m8n8.x4.shared.b16 {%0,%1,%2,%3}, [%4];"
                             : "=r"(bf[ntl][0]), "=r"(bf[ntl][1]), "=r"(bf[ntl][2]), "=r"(bf[ntl][3])
                             : "r"(addr));
            }
#pragma unroll
            for (int mtl = 0; mtl < 4; mtl++) {
                uint32_t af[4];
                uint32_t addr = sa + swz(arow + mtl * 16, acol + ks * 16);
                asm volatile("ldmatrix.sync.aligned.m8n8.x4.shared.b16 {%0,%1,%2,%3}, [%4];"
                             : "=r"(af[0]), "=r"(af[1]), "=r"(af[2]), "=r"(af[3])
                             : "r"(addr));
#pragma unroll
                for (int ntl = 0; ntl < 2; ntl++) {
#pragma unroll
                    for (int h = 0; h < 2; h++) {
                        float* d = acc[mtl][ntl * 2 + h];
                        asm volatile(
                            "mma.sync.aligned.m16n8k16.row.col.f32.bf16.bf16.f32 "
                            "{%0,%1,%2,%3}, {%4,%5,%6,%7}, {%8,%9}, {%0,%1,%2,%3};"
                            : "+f"(d[0]), "+f"(d[1]), "+f"(d[2]), "+f"(d[3])
                            : "r"(af[0]), "r"(af[1]), "r"(af[2]), "r"(af[3]),
                              "r"(bf[ntl][2 * h]), "r"(bf[ntl][2 * h + 1]));
                    }
                }
            }
        }
        __syncthreads();
    }

    // epilogue: c-frag -> global (+ optional bias / row gather)
    float* cb = Cout + (size_t)blockIdx.y * (size_t)partstride;
    int g = lane >> 2, t = lane & 3;
    int mbase = mt * 128 + wm * 64;
    int nbase = nt * 128 + wn * 32;
#pragma unroll
    for (int mtl = 0; mtl < 4; mtl++) {
        int r0 = mbase + mtl * 16 + g;
        int r1 = r0 + 8;
        float bv0 = 0.f, bv1 = 0.f;
        if (bias) {
            if (r0 < M) bv0 = bias[bidx ? bidx[r0] : r0];
            if (r1 < M) bv1 = bias[bidx ? bidx[r1] : r1];
        }
#pragma unroll
        for (int ns = 0; ns < 4; ns++) {
            int col = nbase + ns * 8 + 2 * t;
            if (r0 < M) {
                float2 v = make_float2(acc[mtl][ns][0] + bv0, acc[mtl][ns][1] + bv0);
                *(float2*)(cb + (size_t)r0 * ldc + col) = v;
            }
            if (r1 < M) {
                float2 v = make_float2(acc[mtl][ns][2] + bv1, acc[mtl][ns][3] + bv1);
                *(float2*)(cb + (size_t)r1 * ldc + col) = v;
            }
        }
    }
}

__global__ void reduce_parts(const float* __restrict__ P, const float* __restrict__ bias,
                             float* __restrict__ C) {
    int idx = blockIdx.x * blockDim.x + threadIdx.x;
    const long MN = (long)NCH * 256;
    if (idx >= MN) return;
    int m = idx >> 8;
    C[idx] = P[idx] + P[MN + idx] + P[2*MN + idx] + P[3*MN + idx] + bias[m];
}

__global__ void argmax_kernel(const float* __restrict__ cosim, int* __restrict__ out) {
    int l = blockIdx.x;
    float bvv = -FLT_MAX; int bii = NCH;
    for (int ch = threadIdx.x; ch < NCH; ch += 256) {
        float v = cosim[(size_t)ch * NL + l];
        if (v > bvv) { bvv = v; bii = ch; }
    }
    __shared__ float sv[256];
    __shared__ int   si[256];
    sv[threadIdx.x] = bvv; si[threadIdx.x] = bii;
    __syncthreads();
    for (int s = 128; s > 0; s >>= 1) {
        if (threadIdx.x < s) {
            float ov = sv[threadIdx.x + s]; int oi = si[threadIdx.x + s];
            if (ov > sv[threadIdx.x] || (ov == sv[threadIdx.x] && oi < si[threadIdx.x])) {
                sv[threadIdx.x] = ov; si[threadIdx.x] = oi;
            }
        }
        __syncthreads();
    }
    if (threadIdx.x == 0) out[l] = si[0];
}

__device__ __forceinline__ float gather_patches(const float* __restrict__ arr,
                                                int Y, int X, int base, int ld) {
    int i1 = Y >> 3, p1 = Y & 7;
    int j1 = X >> 3, q1 = X & 7;
    float s = 0.f;
#pragma unroll
    for (int dy = 0; dy < 2; dy++) {
        int i = i1 - dy;
        if (i < 0 || i > 62) continue;
        int p = p1 + 8 * dy;
#pragma unroll
        for (int dx = 0; dx < 2; dx++) {
            int j = j1 - dx;
            if (j < 0 || j > 62) continue;
            int q = q1 + 8 * dx;
            s += arr[(size_t)(i * 63 + j) * ld + base + p * 16 + q];
        }
    }
    return s;
}
__device__ __forceinline__ int cov(int y) {
    int lo = (y <= 15) ? 0 : ((y - 8) >> 3);
    int hi = min(62, y >> 3);
    return hi - lo + 1;
}
__global__ void mr_kernel(const float* __restrict__ OM, float* __restrict__ MR) {
    int idx = blockIdx.x * blockDim.x + threadIdx.x;
    if (idx >= 512 * 512) return;
    int y = idx >> 9, x = idx & 511;
    MR[idx] = gather_patches(OM, y, x, 768, 1024);
}
__global__ void out_epi(const float* __restrict__ OM, float* __restrict__ out) {
    int idx = blockIdx.x * blockDim.x + threadIdx.x;
    if (idx >= OUT_ELEMS) return;
    int oc = idx / 254016;
    int r  = idx - oc * 254016;
    int Y  = r / 504 + 4;
    int X  = r - (r / 504) * 504 + 4;
    out[idx] = gather_patches(OM, Y, X, oc << 8, 1024);
}
__global__ void hole_epi(const float* __restrict__ MR,
                         const float* __restrict__ up2w, const float* __restrict__ up2b,
                         const float* __restrict__ up3w, const float* __restrict__ up3b,
                         float* __restrict__ out) {
    int idx = blockIdx.x * blockDim.x + threadIdx.x;
    if (idx >= HOLE_ELEMS) return;
    int c  = idx / 1032256;
    int r  = idx - c * 1032256;
    int Yh = r / 1016;
    int Xh = r - Yh * 1016;
    int Yu = Yh + 4, Xu = Xh + 4;
    int y = Yu >> 1, ky = Yu & 1;
    int x = Xu >> 1, kx = Xu & 1;
    float mr = MR[(y << 9) + x];
    float wm = (float)(cov(y) * cov(x));
    float num = mr * up2w[c * 4 + ky * 2 + kx] + up2b[c];
    float den = wm * up3w[ky * 2 + kx] + up3b[0];
    out[idx] = num / den;
}
__global__ void raw_epi(const float* __restrict__ RK, float* __restrict__ out) {
    int idx = blockIdx.x * blockDim.x + threadIdx.x;
    if (idx >= RAW_ELEMS) return;
    int oc = idx / 254016;
    int r  = idx - oc * 254016;
    int Y  = r / 504 + 4;
    int X  = r - (r / 504) * 504 + 4;
    float s  = gather_patches(RK, Y, X, oc << 8, 4608);
    float wm = (float)(cov(Y) * cov(X));
    out[idx] = s / wm;
}

extern "C" void kernel_launch(void* const* d_in, const int* in_sizes, int n_in,
                              void* d_out, int out_size) {
    (void)in_sizes; (void)n_in; (void)out_size;
    const float* cosim = (const float*)d_in[0];
    const float* b     = (const float*)d_in[1];
    const float* mask  = (const float*)d_in[2];
    const float* aux   = (const float*)d_in[3];
    const float* w1    = (const float*)d_in[4];
    const float* b1    = (const float*)d_in[5];
    const float* w2    = (const float*)d_in[6];
    const float* b2    = (const float*)d_in[7];
    const float* wa    = (const float*)d_in[8];
    const float* ba    = (const float*)d_in[9];
    const float* up2w  = (const float*)d_in[10];
    const float* up2b  = (const float*)d_in[11];
    const float* up3w  = (const float*)d_in[12];
    const float* up3b  = (const float*)d_in[13];
    float* out = (float*)d_out;

    bf16 *A1, *A2, *AA, *A3, *B1, *B2, *BA, *B3;
    float *C1, *C2, *P2, *OM, *RK, *MR;
    int* AM;
    cudaGetSymbolAddress((void**)&A1, g_A1);
    cudaGetSymbolAddress((void**)&A2, g_A2);
    cudaGetSymbolAddress((void**)&AA, g_AA);
    cudaGetSymbolAddress((void**)&A3, g_A3);
    cudaGetSymbolAddress((void**)&B1, g_B1);
    cudaGetSymbolAddress((void**)&B2, g_B2);
    cudaGetSymbolAddress((void**)&BA, g_BA);
    cudaGetSymbolAddress((void**)&B3, g_B3);
    cudaGetSymbolAddress((void**)&C1, g_C1);
    cudaGetSymbolAddress((void**)&C2, g_C2);
    cudaGetSymbolAddress((void**)&P2, g_P2);
    cudaGetSymbolAddress((void**)&OM, g_OM);
    cudaGetSymbolAddress((void**)&RK, g_RK);
    cudaGetSymbolAddress((void**)&MR, g_MR);
    cudaGetSymbolAddress((void**)&AM, g_AMAX);

    cudaFuncSetAttribute(gemm_tc, cudaFuncAttributeMaxDynamicSharedMemorySize, 65536);

    argmax_kernel<<<NL, 256>>>(cosim, AM);

    { long t = (long)NCH * K1; split_rowmajor<<<(unsigned)((t+255)/256), 256>>>(w1, A1, NCH, K1, KT1, nullptr); }
    { long t = (long)NCH * K2; split_rowmajor<<<(unsigned)((t+255)/256), 256>>>(w2, A2, NCH, K2, KT2, nullptr); }
    { long t = (long)NL  * K1; split_rowmajor<<<(unsigned)((t+255)/256), 256>>>(wa, AA, NL, K1, KT1, AM); }
    { long t = (long)768 * K1; split_patches<<<(unsigned)((t+255)/256), 256>>>(b, B1, 3, 768, K1, KT1, 0); }
    { long t = (long)256 * K2; split_patches<<<(unsigned)((t+255)/256), 256>>>(mask, B2, 6, 256, K2, KT2, 1); }
    { long t = (long)4608* K1; split_patches<<<(unsigned)((t+255)/256), 256>>>(aux, BA, 18, 4608, K1, KT1, 0); }
    transsplit_cos<<<dim3(KT3, 32), 128>>>(cosim, A3);

    // GEMM1: C1 = w1 @ BP^T + b1   (5766 x 768)
    gemm_tc<<<dim3(46*6, 1), 256, 65536>>>(A1, B1, KT1, KT1, 6, C1, NCH, 768, b1, nullptr, 0);
    // GEMM2 split-K=4: P2 partials, then reduce (+b2)   (5766 x 256)
    gemm_tc<<<dim3(46*2, 4), 256, 65536>>>(A2, B2, KT2, 280, 2, P2, NCH, 256, nullptr, nullptr, (long)NCH*256);
    reduce_parts<<<(NCH*256 + 255)/256, 256>>>(P2, b2, C2);
    transsplit_bkg<<<dim3(KT3, 8), 128>>>(C1, C2, B3);
    // GEMM3: OM = cos^T @ [bkg|msk]^T   (3969 x 1024)
    gemm_tc<<<dim3(32*8, 1), 256, 65536>>>(A3, B3, KT3, KT3, 8, OM, NL, 1024, nullptr, nullptr, 0);
    // GEMM5: RK = wa[amax] @ AP^T + ba[amax]   (3969 x 4608)
    gemm_tc<<<dim3(32*36, 1), 256, 65536>>>(AA, BA, KT1, KT1, 36, RK, NL, 4608, ba, AM, 0);

    mr_kernel<<<(512*512 + 255)/256, 256>>>(OM, MR);
    out_epi <<<(OUT_ELEMS  + 255)/256, 256>>>(OM, out);
    hole_epi<<<(HOLE_ELEMS + 255)/256, 256>>>(MR, up2w, up2b, up3w, up3b, out + HOLE_OFF);
    raw_epi <<<(RAW_ELEMS  + 255)/256, 256>>>(RK, out + RAW_OFF);
}